// round 5
// baseline (speedup 1.0000x reference)
#include <cuda_runtime.h>
#include <cuda_bf16.h>
#include <math.h>
#include <stdint.h>

#define NB 256
#define TT 64
#define HH 1024
#define GG 4096
#define LL 16
#define KP 3072   // 3-term split folded into K

__device__ __forceinline__ uint32_t smem_u32(const void* p) {
    uint32_t a;
    asm("{ .reg .u64 t; cvta.to.shared.u64 t, %1; cvt.u32.u64 %0, t; }" : "=r"(a) : "l"(p));
    return a;
}
#define CP16(dst, src) asm volatile("cp.async.cg.shared.global [%0], [%1], 16;" :: "r"(dst), "l"(src) : "memory")
#define CP_COMMIT() asm volatile("cp.async.commit_group;" ::: "memory")
#define CP_WAIT1() asm volatile("cp.async.wait_group 1;" ::: "memory")
#define LDSM4(r0, r1, r2, r3, addr) \
    asm volatile("ldmatrix.sync.aligned.m8n8.x4.shared.b16 {%0,%1,%2,%3}, [%4];" \
        : "=r"(r0), "=r"(r1), "=r"(r2), "=r"(r3) : "r"(addr))
#define MMA16816(d, a, b) \
    asm volatile("mma.sync.aligned.m16n8k16.row.col.f32.bf16.bf16.f32 " \
        "{%0,%1,%2,%3}, {%4,%5,%6,%7}, {%8,%9}, {%0,%1,%2,%3};" \
        : "+f"((d)[0]), "+f"((d)[1]), "+f"((d)[2]), "+f"((d)[3]) \
        : "r"((a)[0]), "r"((a)[1]), "r"((a)[2]), "r"((a)[3]), "r"((b)[0]), "r"((b)[1]))

// ------------------------------------------------ scratch
__device__ float g_XW[(size_t)NB * TT * GG];      // permuted cols, fp32
__device__ float g_P[(size_t)NB * LL * GG];       // permuted cols, fp32
__device__ float g_AT[(size_t)NB * LL * HH];      // fp32 for scores
__device__ float g_w[NB * LL];
__device__ float g_h[NB * HH];
__device__ float g_c[NB * HH];
__device__ float g_bperm[GG];
__device__ volatile unsigned g_bar;
__device__ __nv_bfloat16 g_xs[(size_t)NB * TT * KP];     // [xhi|xlo|xhi]
__device__ __nv_bfloat16 g_ATs[(size_t)NB * LL * KP];    // [hi|lo|hi]
__device__ __nv_bfloat16 g_Wxs[(size_t)GG * KP];         // [hi|hi|lo] (B side)
__device__ __nv_bfloat16 g_Whs[(size_t)GG * KP];
__device__ __nv_bfloat16 g_Was[(size_t)GG * KP];
__device__ __nv_bfloat16 g_hsA[(size_t)NB * KP];         // h ping [hi|lo|hi]
__device__ __nv_bfloat16 g_hsB[(size_t)NB * KP];         // h pong

// ------------------------------------------------ prep kernels
__global__ void x_split_kernel(const float* __restrict__ x) {
    size_t gid = (size_t)blockIdx.x * 256 + threadIdx.x;  // float4 id
    size_t r = gid >> 8;
    int kq = (int)(gid & 255);
    float4 v = ((const float4*)x)[gid];
    __nv_bfloat162 h0 = __floats2bfloat162_rn(v.x, v.y);
    __nv_bfloat162 h1 = __floats2bfloat162_rn(v.z, v.w);
    float2 f0 = __bfloat1622float2(h0), f1 = __bfloat1622float2(h1);
    __nv_bfloat162 l0 = __floats2bfloat162_rn(v.x - f0.x, v.y - f0.y);
    __nv_bfloat162 l1 = __floats2bfloat162_rn(v.z - f1.x, v.w - f1.y);
    __nv_bfloat162* base = (__nv_bfloat162*)(g_xs + r * KP);
    base[kq * 2] = h0;         base[kq * 2 + 1] = h1;
    base[512 + kq * 2] = l0;   base[512 + kq * 2 + 1] = l1;
    base[1024 + kq * 2] = h0;  base[1024 + kq * 2 + 1] = h1;
}

__global__ void at_prep_kernel(const float* __restrict__ A) {
    int idx = blockIdx.x * 256 + threadIdx.x;  // n*1024 + h
    int n = idx >> 10, h = idx & 1023;
    const float4* a4 = (const float4*)(A + (size_t)idx * 16);
    float s = 0.f;
#pragma unroll
    for (int q = 0; q < 4; q++) {
        float4 v = a4[q];
        float vv[4] = {v.x, v.y, v.z, v.w};
#pragma unroll
        for (int e = 0; e < 4; e++) {
            int l = q * 4 + e;
            float val = vv[e];
            g_AT[((size_t)n * LL + l) * HH + h] = val;
            __nv_bfloat16 hi = __float2bfloat16(val);
            __nv_bfloat16 lo = __float2bfloat16(val - __bfloat162float(hi));
            size_t o = ((size_t)n * LL + l) * KP + h;
            g_ATs[o] = hi; g_ATs[o + 1024] = lo; g_ATs[o + 2048] = hi;
            s += val;
        }
    }
    float h0 = s * (1.0f / 16.0f);
    g_h[idx] = h0;
    g_c[idx] = h0;
    __nv_bfloat16 hh = __float2bfloat16(h0);
    __nv_bfloat16 hl = __float2bfloat16(h0 - __bfloat162float(hh));
    size_t o = (size_t)n * KP + h;
    g_hsA[o] = hh; g_hsA[o + 1024] = hl; g_hsA[o + 2048] = hh;
}

// transpose + split + permute: col c = g*1024+u -> rp = ((u>>3)<<5)|(g<<3)|(u&7)
__global__ void wsplit_kernel(const float* __restrict__ W, __nv_bfloat16* __restrict__ Ws) {
    __shared__ float tile[32][33];
    int c0 = blockIdx.x * 32, k0 = blockIdx.y * 32;
    int tx = threadIdx.x;
    for (int i = threadIdx.y; i < 32; i += 8)
        tile[i][tx] = W[(size_t)(k0 + i) * GG + c0 + tx];
    __syncthreads();
    for (int i = threadIdx.y; i < 32; i += 8) {
        int c = c0 + i;
        int u = c & 1023, g = c >> 10;
        int rp = ((u >> 3) << 5) | (g << 3) | (u & 7);
        float v = tile[tx][i];
        __nv_bfloat16 hi = __float2bfloat16(v);
        __nv_bfloat16 lo = __float2bfloat16(v - __bfloat162float(hi));
        size_t o = (size_t)rp * KP + k0 + tx;
        Ws[o] = hi; Ws[o + 1024] = hi; Ws[o + 2048] = lo;
    }
}

__global__ void bias_perm_kernel(const float* __restrict__ b) {
    int idx = blockIdx.x * 256 + threadIdx.x;   // permuted col
    int g = (idx >> 3) & 3;
    int u = (idx & 7) | ((idx >> 5) << 3);
    g_bperm[idx] = b[g * 1024 + u];
    if (idx == 0) g_bar = 0;                    // reset grid barrier each launch
}

// ------------------------------------------------ phase-1 mma.sync bf16 GEMM
template <int BM, int BN, int WARPS_M, int WARPS_N, int EPI>
__global__ void __launch_bounds__(WARPS_M * WARPS_N * 32)
gemm_mma(const __nv_bfloat16* __restrict__ Ag, const __nv_bfloat16* __restrict__ Bg,
         float* __restrict__ Cout, const float* __restrict__ addv)
{
    constexpr int NTH = WARPS_M * WARPS_N * 32;
    constexpr int WM = BM / WARPS_M, WN = BN / WARPS_N;
    constexpr int MT = WM / 16, NT2 = WN / 8;
    constexpr int KC = KP / 64;
    constexpr int ABUF = BM * 128, BBUF = BN * 128;

    extern __shared__ char smem[];
    const uint32_t sA = smem_u32(smem);
    const uint32_t sB = sA + 2 * ABUF;
    const int tid = threadIdx.x, lane = tid & 31, warp = tid >> 5;
    const int wm0 = (warp / WARPS_N) * WM, wn0 = (warp % WARPS_N) * WN;
    const int m0 = blockIdx.y * BM, n0 = blockIdx.x * BN;
    const __nv_bfloat16* Abase = Ag + (size_t)m0 * KP;
    const __nv_bfloat16* Bbase = Bg + (size_t)n0 * KP;

    float acc[MT][NT2][4];
#pragma unroll
    for (int i = 0; i < MT; i++)
#pragma unroll
        for (int j = 0; j < NT2; j++)
#pragma unroll
            for (int e = 0; e < 4; e++) acc[i][j][e] = 0.f;

#define ISSUE1(kc, buf) do { \
    const __nv_bfloat16* As_ = Abase + (kc) * 64; \
    _Pragma("unroll") \
    for (int i = 0; i < BM * 8 / NTH; i++) { \
        int idx = tid + i * NTH, r = idx >> 3, q = idx & 7; \
        CP16(sA + (buf) * ABUF + r * 128 + (((q ^ (r & 7)) << 4)), As_ + (size_t)r * KP + q * 8); \
    } \
    const __nv_bfloat16* Bs_ = Bbase + (kc) * 64; \
    _Pragma("unroll") \
    for (int i = 0; i < BN * 8 / NTH; i++) { \
        int idx = tid + i * NTH, r = idx >> 3, q = idx & 7; \
        CP16(sB + (buf) * BBUF + r * 128 + (((q ^ (r & 7)) << 4)), Bs_ + (size_t)r * KP + q * 8); \
    } \
} while (0)

    ISSUE1(0, 0); CP_COMMIT();
    ISSUE1(1, 1); CP_COMMIT();

    for (int kc = 0; kc < KC; kc++) {
        CP_WAIT1();
        __syncthreads();
        const int buf = kc & 1;
        const uint32_t a0b = sA + buf * ABUF, b0b = sB + buf * BBUF;
#pragma unroll
        for (int ks = 0; ks < 4; ks++) {
            uint32_t af[MT][4], bf[NT2][2];
#pragma unroll
            for (int mt = 0; mt < MT; mt++) {
                int r = wm0 + mt * 16 + (lane & 15);
                int q = ks * 2 + (lane >> 4);
                LDSM4(af[mt][0], af[mt][1], af[mt][2], af[mt][3],
                      a0b + r * 128 + (((q ^ (r & 7)) << 4)));
            }
#pragma unroll
            for (int p = 0; p < NT2 / 2; p++) {
                int n = wn0 + p * 16 + (lane & 7) + ((lane >> 4) << 3);
                int q = ks * 2 + ((lane >> 3) & 1);
                LDSM4(bf[2 * p][0], bf[2 * p][1], bf[2 * p + 1][0], bf[2 * p + 1][1],
                      b0b + n * 128 + (((q ^ (n & 7)) << 4)));
            }
#pragma unroll
            for (int mt = 0; mt < MT; mt++)
#pragma unroll
                for (int nt = 0; nt < NT2; nt++)
                    MMA16816(acc[mt][nt], af[mt], bf[nt]);
        }
        __syncthreads();
        if (kc + 2 < KC) ISSUE1(kc + 2, buf);
        CP_COMMIT();
    }
#undef ISSUE1

    const int l4 = lane >> 2, q2 = (lane & 3) * 2;
#pragma unroll
    for (int mt = 0; mt < MT; mt++) {
        int r0 = m0 + wm0 + mt * 16 + l4;
#pragma unroll
        for (int nt = 0; nt < NT2; nt++) {
            int col = n0 + wn0 + nt * 8 + q2;
            float bx = 0.f, by = 0.f;
            if (EPI == 1) { bx = addv[col]; by = addv[col + 1]; }
            *(float2*)(Cout + (size_t)r0 * GG + col) =
                make_float2(acc[mt][nt][0] + bx, acc[mt][nt][1] + by);
            *(float2*)(Cout + (size_t)(r0 + 8) * GG + col) =
                make_float2(acc[mt][nt][2] + bx, acc[mt][nt][3] + by);
        }
    }
}

// ------------------------------------------------ persistent scan kernel
// 256 CTAs x 256 threads. Per step: scores (CTA=n) -> barrier -> 64x64 GEMM
// (CTA=(nb,ub)) with fused attn-combine + LSTM gates epilogue -> barrier.
__global__ void __launch_bounds__(256, 2)
scan_kernel(float* __restrict__ out)
{
    extern __shared__ char smem[];
    __shared__ float s_sc[16];
    const uint32_t sA = smem_u32(smem);
    const uint32_t sB = sA + 2 * 64 * 128;
    const int tid = threadIdx.x, lane = tid & 31, warp = tid >> 5;
    const int bid = blockIdx.x;
    // gemm mapping: WARPS_M=4, WARPS_N=2 -> WM=16, WN=32, MT=1, NT2=4
    const int wm0 = (warp >> 1) * 16, wn0 = (warp & 1) * 32;
    const int nb = bid >> 6, ub = bid & 63;
    const int m0 = nb * 64, n0c = ub * 64;
    const int l4 = lane >> 2, q2 = (lane & 3) * 2;
    const int U0 = (((n0c + wn0) >> 5) << 3) + q2;
    const int cb = n0c + wn0 + q2;

    unsigned tgt = 256;

    for (int t = 0; t < TT; t++) {
        // ---- phase A: scores + softmax for n = bid ----
        {
            const int n = bid;
            const float* hp = g_h + (size_t)n * HH;
            const float* a0 = g_AT + ((size_t)n * LL + warp) * HH;
            const float* a1 = a0 + 8 * HH;
            float acc0 = 0.f, acc1 = 0.f;
            for (int k = lane; k < HH; k += 32) {
                float hv = __ldcg(hp + k);
                acc0 += hv * a0[k];
                acc1 += hv * a1[k];
            }
#pragma unroll
            for (int o = 16; o > 0; o >>= 1) {
                acc0 += __shfl_xor_sync(0xffffffffu, acc0, o);
                acc1 += __shfl_xor_sync(0xffffffffu, acc1, o);
            }
            if (lane == 0) { s_sc[warp] = acc0 * 0.03125f; s_sc[warp + 8] = acc1 * 0.03125f; }
            __syncthreads();
            if (warp == 0) {
                float s = (lane < 16) ? s_sc[lane] : -1e30f;
                float m = s;
#pragma unroll
                for (int o = 16; o > 0; o >>= 1) m = fmaxf(m, __shfl_xor_sync(0xffffffffu, m, o));
                float e = (lane < 16) ? expf(s - m) : 0.f;
                float tot = e;
#pragma unroll
                for (int o = 16; o > 0; o >>= 1) tot += __shfl_xor_sync(0xffffffffu, tot, o);
                if (lane < 16) g_w[n * LL + lane] = e / tot;
            }
        }
        // ---- barrier 1 ----
        __syncthreads();
        if (tid == 0) {
            __threadfence();
            atomicAdd((unsigned*)&g_bar, 1u);
            while (g_bar < tgt) __nanosleep(32);
        }
        __syncthreads();
        tgt += 256;

        // ---- phase B: 64x64 GEMM over K'=3072 + fused epilogue ----
        const __nv_bfloat16* hcur = (t & 1) ? g_hsB : g_hsA;
        __nv_bfloat16* hnxt = (t & 1) ? (__nv_bfloat16*)g_hsA : (__nv_bfloat16*)g_hsB;
        const __nv_bfloat16* Abase = hcur + (size_t)m0 * KP;
        const __nv_bfloat16* Bbase = g_Whs + (size_t)n0c * KP;

        float acc[4][4];
#pragma unroll
        for (int j = 0; j < 4; j++)
#pragma unroll
            for (int e = 0; e < 4; e++) acc[j][e] = 0.f;

#define ISSUE2(kc, buf) do { \
    const __nv_bfloat16* As_ = Abase + (kc) * 64; \
    _Pragma("unroll") \
    for (int i = 0; i < 2; i++) { \
        int idx = tid + i * 256, r = idx >> 3, q = idx & 7; \
        CP16(sA + (buf) * 8192 + r * 128 + (((q ^ (r & 7)) << 4)), As_ + (size_t)r * KP + q * 8); \
    } \
    const __nv_bfloat16* Bs_ = Bbase + (kc) * 64; \
    _Pragma("unroll") \
    for (int i = 0; i < 2; i++) { \
        int idx = tid + i * 256, r = idx >> 3, q = idx & 7; \
        CP16(sB + (buf) * 8192 + r * 128 + (((q ^ (r & 7)) << 4)), Bs_ + (size_t)r * KP + q * 8); \
    } \
} while (0)

        ISSUE2(0, 0); CP_COMMIT();
        ISSUE2(1, 1); CP_COMMIT();

        for (int kc = 0; kc < KP / 64; kc++) {
            CP_WAIT1();
            __syncthreads();
            const int buf = kc & 1;
            const uint32_t a0b = sA + buf * 8192, b0b = sB + buf * 8192;
#pragma unroll
            for (int ks = 0; ks < 4; ks++) {
                uint32_t af[4], bf[4][2];
                {
                    int r = wm0 + (lane & 15);
                    int q = ks * 2 + (lane >> 4);
                    LDSM4(af[0], af[1], af[2], af[3],
                          a0b + r * 128 + (((q ^ (r & 7)) << 4)));
                }
#pragma unroll
                for (int p = 0; p < 2; p++) {
                    int n = wn0 + p * 16 + (lane & 7) + ((lane >> 4) << 3);
                    int q = ks * 2 + ((lane >> 3) & 1);
                    LDSM4(bf[2 * p][0], bf[2 * p][1], bf[2 * p + 1][0], bf[2 * p + 1][1],
                          b0b + n * 128 + (((q ^ (n & 7)) << 4)));
                }
#pragma unroll
                for (int nt = 0; nt < 4; nt++)
                    MMA16816(acc[nt], af, bf[nt]);
            }
            __syncthreads();
            if (kc + 2 < KP / 64) ISSUE2(kc + 2, buf);
            CP_COMMIT();
        }
#undef ISSUE2

        // epilogue: z = XW + sum_l w_l * P, gates, state update
#pragma unroll
        for (int rs = 0; rs < 2; rs++) {
            const int row = m0 + wm0 + l4 + rs * 8;   // row == n
            float wv[16];
#pragma unroll
            for (int l = 0; l < 16; l++) wv[l] = __ldcg(&g_w[row * LL + l]);
            const float* xr = g_XW + ((size_t)row * TT + t) * GG + cb;
            const float* pr = g_P + (size_t)row * LL * GG + cb;
            float z[4][2];
#pragma unroll
            for (int nt = 0; nt < 4; nt++) {
                float2 zv = *(const float2*)(xr + nt * 8);
#pragma unroll
                for (int l = 0; l < 16; l++) {
                    float2 pv = *(const float2*)(pr + (size_t)l * GG + nt * 8);
                    zv.x += wv[l] * pv.x; zv.y += wv[l] * pv.y;
                }
                z[nt][0] = zv.x; z[nt][1] = zv.y;
            }
#pragma unroll
            for (int us = 0; us < 2; us++) {
                float ai = acc[0][rs * 2 + us] + z[0][us];
                float afv = acc[1][rs * 2 + us] + z[1][us];
                float ao = acc[2][rs * 2 + us] + z[2][us];
                float ag = acc[3][rs * 2 + us] + z[3][us];
                int u = U0 + us;
                float gi = 1.f / (1.f + expf(-ai));
                float gf = 1.f / (1.f + expf(-afv));
                float go = 1.f / (1.f + expf(-ao));
                float gg = tanhf(ag);
                size_t hx = (size_t)row * HH + u;
                float cn = gf * g_c[hx] + gi * gg;
                g_c[hx] = cn;
                float hn = go * tanhf(cn);
                g_h[hx] = hn;
                __nv_bfloat16 hh = __float2bfloat16(hn);
                __nv_bfloat16 hl = __float2bfloat16(hn - __bfloat162float(hh));
                size_t hb = (size_t)row * KP + u;
                hnxt[hb] = hh; hnxt[hb + 1024] = hl; hnxt[hb + 2048] = hh;
                out[((size_t)row * TT + t) * HH + u] = hn;
            }
        }

        // ---- barrier 2 ----
        __syncthreads();
        if (tid == 0) {
            __threadfence();
            atomicAdd((unsigned*)&g_bar, 1u);
            while (g_bar < tgt) __nanosleep(32);
        }
        __syncthreads();
        tgt += 256;
    }
}

// ------------------------------------------------ launch
extern "C" void kernel_launch(void* const* d_in, const int* in_sizes, int n_in,
                              void* d_out, int out_size) {
    const float* x = (const float*)d_in[0];
    const float* A = (const float*)d_in[1];
    const float* Wx = (const float*)d_in[2];
    const float* Wh = (const float*)d_in[3];
    const float* Wattn = (const float*)d_in[4];
    const float* b = (const float*)d_in[5];
    float* out = (float*)d_out;

    float *p_xw, *p_p, *p_bp;
    __nv_bfloat16 *p_xs, *p_ats, *p_wxs, *p_whs, *p_was;
    cudaGetSymbolAddress((void**)&p_xw, g_XW);
    cudaGetSymbolAddress((void**)&p_p, g_P);
    cudaGetSymbolAddress((void**)&p_bp, g_bperm);
    cudaGetSymbolAddress((void**)&p_xs, g_xs);
    cudaGetSymbolAddress((void**)&p_ats, g_ATs);
    cudaGetSymbolAddress((void**)&p_wxs, g_Wxs);
    cudaGetSymbolAddress((void**)&p_whs, g_Whs);
    cudaGetSymbolAddress((void**)&p_was, g_Was);

    constexpr int SM_P1 = 2 * (128 + 128) * 128;  // 65536
    constexpr int SM_SC = 2 * (64 + 64) * 128;    // 32768
    cudaFuncSetAttribute((const void*)gemm_mma<128, 128, 2, 4, 1>,
                         cudaFuncAttributeMaxDynamicSharedMemorySize, SM_P1);
    cudaFuncSetAttribute((const void*)gemm_mma<128, 128, 2, 4, 0>,
                         cudaFuncAttributeMaxDynamicSharedMemorySize, SM_P1);

    // prep
    x_split_kernel<<<(NB * TT * HH / 4) / 256, 256>>>(x);
    at_prep_kernel<<<(NB * HH) / 256, 256>>>(A);
    {
        dim3 g(GG / 32, HH / 32), blk(32, 8);
        wsplit_kernel<<<g, blk>>>(Wx, p_wxs);
        wsplit_kernel<<<g, blk>>>(Wh, p_whs);
        wsplit_kernel<<<g, blk>>>(Wattn, p_was);
    }
    bias_perm_kernel<<<GG / 256, 256>>>(b);

    // phase 1: XW = x' @ Wx'^T + b ; P = AT' @ Wa'^T
    {
        dim3 g(GG / 128, (NB * TT) / 128);
        gemm_mma<128, 128, 2, 4, 1><<<g, 256, SM_P1>>>(p_xs, p_wxs, p_xw, p_bp);
    }
    {
        dim3 g(GG / 128, (NB * LL) / 128);
        gemm_mma<128, 128, 2, 4, 0><<<g, 256, SM_P1>>>(p_ats, p_was, p_p, nullptr);
    }

    // phase 2: one persistent kernel for the whole 64-step scan
    scan_kernel<<<NB, 256, SM_SC>>>(out);
}